// round 5
// baseline (speedup 1.0000x reference)
#include <cuda_runtime.h>
#include <math.h>

// ----------------------------------------------------------------------------
// AUGGCN: 2-layer GCN + linear head + sigmoid
//   deg/dinv -> xw = x@W1 -> scatter1(norm) +b1,relu -> @W2 -> scatter2(norm)
//   -> +b2,relu -> @Wc+bc -> sigmoid
// Edge-index dtype (int32 vs int64) detected at runtime on-device.
// R4/R5: GEMM1 on packed fp32x2 FFMA2 (2 FMA/instr, sm_103a only) —
// resubmitted unchanged after broker timeout; awaiting first measurement.
// ----------------------------------------------------------------------------

#define MAXN 100000
#define FDIM 165
#define H1DIM 128
#define H2DIM 2

typedef unsigned long long ull;

// Scratch (device globals; no allocations allowed)
__device__ __align__(16) float g_deg[MAXN];
__device__ __align__(16) float g_dinv[MAXN];
__device__ __align__(16) float g_xw[(size_t)MAXN * H1DIM];   // x @ W1
__device__ __align__(16) float g_h1[(size_t)MAXN * H1DIM];   // scatter accum L1
__device__ __align__(16) float g_h2w[(size_t)MAXN * H2DIM];  // relu(h1+b1) @ W2
__device__ __align__(16) float g_h2[(size_t)MAXN * H2DIM];   // scatter accum L2
__device__ int g_is64;                                        // edge dtype flag

// ---------------- edge-index access (dtype-agnostic) ------------------------
__device__ __forceinline__ int edge_at(const void* ei, long long pos, int is64) {
    if (is64) return (int)((const long long*)ei)[pos];
    return ((const int*)ei)[pos];
}

// ---------------- vector global reductions (sm_90+) -------------------------
__device__ __forceinline__ void red_add_v4(float* p, float4 v) {
    asm volatile("red.global.add.v4.f32 [%0], {%1,%2,%3,%4};"
                 :: "l"(p), "f"(v.x), "f"(v.y), "f"(v.z), "f"(v.w) : "memory");
}
__device__ __forceinline__ void red_add_v2(float* p, float a, float b) {
    asm volatile("red.global.add.v2.f32 [%0], {%1,%2};"
                 :: "l"(p), "f"(a), "f"(b) : "memory");
}

// ---------------- packed fp32x2 FMA (sm_103a FFMA2) -------------------------
__device__ __forceinline__ void ffma2(ull& d, ull a, ull b) {
    asm("fma.rn.f32x2 %0, %1, %2, %0;" : "+l"(d) : "l"(a), "l"(b));
}
__device__ __forceinline__ void unpack2(ull v, float& lo, float& hi) {
    asm("mov.b64 {%0, %1}, %2;" : "=f"(lo), "=f"(hi) : "l"(v));
}

// ---------------- init: zero accum, deg=1 (self loop), dtype detect ---------
__global__ void k_init(const int* __restrict__ ei32, int n) {
    long long i = (long long)blockIdx.x * blockDim.x + threadIdx.x;
    if (i == 0) {
        int all_zero = 1;
#pragma unroll 8
        for (int t = 0; t < 64; t++)
            if (ei32[2 * t + 1] != 0) { all_zero = 0; break; }
        g_is64 = all_zero;
    }
    long long tot = (long long)n * H1DIM;
    if (i < tot) g_h1[i] = 0.f;
    if (i < (long long)n * H2DIM) g_h2[i] = 0.f;
    if (i < n) g_deg[i] = 1.0f;   // self loop contributes 1 to dst degree
}

// ---------------- degree over edges -----------------------------------------
__global__ void k_degree(const void* __restrict__ ei, int E) {
    int e = blockIdx.x * blockDim.x + threadIdx.x;
    if (e >= E) return;
    int is64 = g_is64;
    int d = edge_at(ei, (long long)E + e, is64);
    atomicAdd(&g_deg[d], 1.0f);
}

__global__ void k_dinv(int n) {
    int i = blockIdx.x * blockDim.x + threadIdx.x;
    if (i < n) g_dinv[i] = rsqrtf(g_deg[i]);
}

// ---------------- GEMM: xw = x @ W1   [n,165] x [165,128] -------------------
// BM=128 rows x 128 cols, BK=16, 256 threads, 8x8 outputs/thread held as
// 32 packed f32x2 accumulators (row pairs). W stored DUPLICATED (w,w) in smem
// so FFMA2 b-operand needs no packing; X row-pairs are natural 64-bit reads.
#define GBM 128
#define GBK 16
__global__ void __launch_bounds__(256) k_gemm1(const float* __restrict__ x,
                                               const float* __restrict__ W1,
                                               int n) {
    __shared__ float  Xs[GBK * GBM];        // [kk][row]  8 KB
    __shared__ float2 Wd[GBK * H1DIM];      // [kk][col] dup (w,w) 16 KB

    const int tid = threadIdx.x;
    const int tx  = tid & 15;               // col group: cols tx*8 .. tx*8+7
    const int ty  = tid >> 4;               // row group: rows ty*8 .. ty*8+7
    const int m0  = blockIdx.x * GBM;

    ull acc[4][8];                          // [rowpair p][col c]
#pragma unroll
    for (int p = 0; p < 4; p++)
#pragma unroll
        for (int c = 0; c < 8; c++) acc[p][c] = 0ULL;

    for (int kb = 0; kb < FDIM; kb += GBK) {
        // ---- load W tile duplicated: 16x128 elems, 8 per thread ----
        {
            int idx0 = tid * 8;             // 0..2047, 8 consecutive cols
            int kk   = idx0 >> 7;
            int col0 = idx0 & 127;
            int kg   = kb + kk;
            if (kg < FDIM) {
                const float4* wr = (const float4*)(W1 + (long long)kg * H1DIM + col0);
                float4 wa = wr[0], wb = wr[1];
                float2* wdst = &Wd[kk * H1DIM + col0];
                wdst[0] = make_float2(wa.x, wa.x);
                wdst[1] = make_float2(wa.y, wa.y);
                wdst[2] = make_float2(wa.z, wa.z);
                wdst[3] = make_float2(wa.w, wa.w);
                wdst[4] = make_float2(wb.x, wb.x);
                wdst[5] = make_float2(wb.y, wb.y);
                wdst[6] = make_float2(wb.z, wb.z);
                wdst[7] = make_float2(wb.w, wb.w);
            } else {
                float2* wdst = &Wd[kk * H1DIM + col0];
#pragma unroll
                for (int j = 0; j < 8; j++) wdst[j] = make_float2(0.f, 0.f);
            }
        }
        // ---- load X tile transposed: row r, kk strip of 8 ----
        {
            int r   = tid & 127;
            int kk0 = (tid >> 7) * 8;       // 0 or 8
            int gm  = m0 + r;
            const float* xr = x + (long long)gm * FDIM + kb + kk0;
#pragma unroll
            for (int j = 0; j < 8; j++) {
                int kg = kb + kk0 + j;
                float v = (gm < n && kg < FDIM) ? xr[j] : 0.f;
                Xs[(kk0 + j) * GBM + r] = v;
            }
        }
        __syncthreads();

#pragma unroll
        for (int kk = 0; kk < GBK; kk++) {
            const ull* xp = (const ull*)&Xs[kk * GBM + ty * 8];       // 4 row pairs
            const ull* wp = (const ull*)&Wd[kk * H1DIM + tx * 8];     // 8 dup pairs
            ull xr_[4], wr_[8];
#pragma unroll
            for (int p = 0; p < 4; p++) xr_[p] = xp[p];
#pragma unroll
            for (int c = 0; c < 8; c++) wr_[c] = wp[c];
#pragma unroll
            for (int c = 0; c < 8; c++)
#pragma unroll
                for (int p = 0; p < 4; p++)
                    ffma2(acc[p][c], xr_[p], wr_[c]);
        }
        __syncthreads();
    }

    // ---- store: rowpair p -> rows m0+ty*8+2p, 2p+1; cols tx*8.. ----
#pragma unroll
    for (int p = 0; p < 4; p++) {
        int gm0 = m0 + ty * 8 + 2 * p;
        float lo[8], hi[8];
#pragma unroll
        for (int c = 0; c < 8; c++) unpack2(acc[p][c], lo[c], hi[c]);
        if (gm0 < n) {
            float4* o = (float4*)&g_xw[(long long)gm0 * H1DIM + tx * 8];
            o[0] = make_float4(lo[0], lo[1], lo[2], lo[3]);
            o[1] = make_float4(lo[4], lo[5], lo[6], lo[7]);
        }
        if (gm0 + 1 < n) {
            float4* o = (float4*)&g_xw[(long long)(gm0 + 1) * H1DIM + tx * 8];
            o[0] = make_float4(hi[0], hi[1], hi[2], hi[3]);
            o[1] = make_float4(hi[4], hi[5], hi[6], hi[7]);
        }
    }
}

// ---------------- scatter1: h1[dst] += xw[src] * norm -----------------------
#define EPW 2
__global__ void __launch_bounds__(512) k_scatter1(const void* __restrict__ ei,
                                                  int E, int n) {
    long long w = ((long long)blockIdx.x * blockDim.x + threadIdx.x) >> 5;
    int lane = threadIdx.x & 31;
    long long tot  = (long long)E + n;
    long long base = w * EPW;
    if (base >= tot) return;
    int is64 = g_is64;

    int s[EPW], d[EPW];
    float nrm[EPW];
#pragma unroll
    for (int j = 0; j < EPW; j++) {
        long long e = base + j;
        if (e >= tot) { s[j] = -1; continue; }
        if (e < E) {
            s[j] = edge_at(ei, e, is64);
            d[j] = edge_at(ei, (long long)E + e, is64);
            nrm[j] = __ldg(&g_dinv[s[j]]) * __ldg(&g_dinv[d[j]]);
        } else {
            s[j] = d[j] = (int)(e - E);
            float di = __ldg(&g_dinv[s[j]]);
            nrm[j] = di * di;
        }
    }
    float4 v[EPW];
#pragma unroll
    for (int j = 0; j < EPW; j++)
        if (s[j] >= 0)
            v[j] = ((const float4*)&g_xw[(long long)s[j] * H1DIM])[lane];
#pragma unroll
    for (int j = 0; j < EPW; j++) {
        if (s[j] < 0) continue;
        float4 t = v[j];
        t.x *= nrm[j]; t.y *= nrm[j]; t.z *= nrm[j]; t.w *= nrm[j];
        red_add_v4(&g_h1[(long long)d[j] * H1DIM + lane * 4], t);
    }
}

// ---------------- layer2 transform: h2w = relu(h1+b1) @ W2  (warp/node) -----
__global__ void k_layer2(const float* __restrict__ b1,
                         const float* __restrict__ W2, int n) {
    int node = (int)(((long long)blockIdx.x * blockDim.x + threadIdx.x) >> 5);
    int lane = threadIdx.x & 31;
    if (node >= n) return;
    float4 v = ((const float4*)&g_h1[(long long)node * H1DIM])[lane];
    float4 b = ((const float4*)b1)[lane];
    v.x = fmaxf(v.x + b.x, 0.f);
    v.y = fmaxf(v.y + b.y, 0.f);
    v.z = fmaxf(v.z + b.z, 0.f);
    v.w = fmaxf(v.w + b.w, 0.f);
    float4 wa = ((const float4*)W2)[lane * 2 + 0];
    float4 wb = ((const float4*)W2)[lane * 2 + 1];
    float a0 = v.x * wa.x + v.y * wa.z + v.z * wb.x + v.w * wb.z;
    float a1 = v.x * wa.y + v.y * wa.w + v.z * wb.y + v.w * wb.w;
#pragma unroll
    for (int off = 16; off > 0; off >>= 1) {
        a0 += __shfl_xor_sync(0xFFFFFFFFu, a0, off);
        a1 += __shfl_xor_sync(0xFFFFFFFFu, a1, off);
    }
    if (lane == 0) {
        g_h2w[(long long)node * 2 + 0] = a0;
        g_h2w[(long long)node * 2 + 1] = a1;
    }
}

// ---------------- scatter2: h2[dst] += h2w[src] * norm  (thread per edge) ---
__global__ void __launch_bounds__(512) k_scatter2(const void* __restrict__ ei,
                                                  int E, int n) {
    long long e = (long long)blockIdx.x * blockDim.x + threadIdx.x;
    long long tot = (long long)E + n;
    if (e >= tot) return;
    int is64 = g_is64;
    int s, d;
    float nrm;
    if (e < E) {
        s = edge_at(ei, e, is64);
        d = edge_at(ei, (long long)E + e, is64);
        nrm = __ldg(&g_dinv[s]) * __ldg(&g_dinv[d]);
    } else {
        s = d = (int)(e - E);
        float di = __ldg(&g_dinv[s]);
        nrm = di * di;
    }
    float2 v = *(const float2*)&g_h2w[(long long)s * 2];
    red_add_v2(&g_h2[(long long)d * 2], v.x * nrm, v.y * nrm);
}

// ---------------- head: out = sigmoid(relu(h2+b2) @ Wc + bc) ----------------
__global__ void k_head(const float* __restrict__ b2,
                       const float* __restrict__ Wc,
                       const float* __restrict__ bc,
                       float* __restrict__ out, int n) {
    int i = blockIdx.x * blockDim.x + threadIdx.x;
    if (i >= n) return;
    float z0 = fmaxf(g_h2[(long long)i * 2 + 0] + b2[0], 0.f);
    float z1 = fmaxf(g_h2[(long long)i * 2 + 1] + b2[1], 0.f);
    float o = z0 * Wc[0] + z1 * Wc[1] + bc[0];
    out[i] = 1.0f / (1.0f + __expf(-o));
}

// ----------------------------------------------------------------------------
extern "C" void kernel_launch(void* const* d_in, const int* in_sizes, int n_in,
                              void* d_out, int out_size) {
    const float* x   = (const float*)d_in[0];
    const void*  ei  = d_in[1];
    const float* W1  = (const float*)d_in[2];
    const float* b1  = (const float*)d_in[3];
    const float* W2  = (const float*)d_in[4];
    const float* b2  = (const float*)d_in[5];
    const float* Wc  = (const float*)d_in[6];
    const float* bc  = (const float*)d_in[7];
    float*       out = (float*)d_out;

    const int n = in_sizes[0] / FDIM;       // 100000
    const int E = in_sizes[1] / 2;          // 1600000

    const int T = 256;
    long long initN = (long long)n * H1DIM;
    k_init<<<(unsigned)((initN + T - 1) / T), T>>>((const int*)ei, n);
    k_degree<<<(E + T - 1) / T, T>>>(ei, E);
    k_dinv<<<(n + T - 1) / T, T>>>(n);
    k_gemm1<<<(n + GBM - 1) / GBM, 256>>>(x, W1, n);

    long long tot   = (long long)E + n;
    long long warps = (tot + EPW - 1) / EPW;
    long long thr1  = warps * 32;
    k_scatter1<<<(unsigned)((thr1 + 511) / 512), 512>>>(ei, E, n);

    long long thr2 = (long long)n * 32;
    k_layer2<<<(unsigned)((thr2 + T - 1) / T), T>>>(b1, W2, n);

    k_scatter2<<<(unsigned)((tot + 511) / 512), 512>>>(ei, E, n);
    k_head<<<(n + T - 1) / T, T>>>(b2, Wc, bc, out, n);
}

// round 6
// speedup vs baseline: 1.6088x; 1.6088x over previous
#include <cuda_runtime.h>
#include <math.h>

// ----------------------------------------------------------------------------
// AUGGCN: 2-layer GCN + linear head + sigmoid
// R6: FFMA2 reverted (smem-bound regression 148->335us). GEMM1 = scalar FFMA,
// 128x128 block, 8x8 thread tile (double FMA density vs R3). Norm factorized:
// xw pre-scaled by dinv[src], consumers post-scale by dinv[dst]; scatters are
// norm-free.
// ----------------------------------------------------------------------------

#define MAXN 100000
#define FDIM 165
#define H1DIM 128
#define H2DIM 2

// Scratch (device globals; no allocations allowed)
__device__ __align__(16) float g_deg[MAXN];
__device__ __align__(16) float g_dinv[MAXN];
__device__ __align__(16) float g_xw[(size_t)MAXN * H1DIM];   // dinv*(x@W1)
__device__ __align__(16) float g_h1[(size_t)MAXN * H1DIM];   // raw scatter L1
__device__ __align__(16) float g_h2w[(size_t)MAXN * H2DIM];  // dinv*(relu@W2)
__device__ __align__(16) float g_h2[(size_t)MAXN * H2DIM];   // raw scatter L2
__device__ int g_is64;                                        // edge dtype flag

// ---------------- edge-index access (dtype-agnostic) ------------------------
__device__ __forceinline__ int edge_at(const void* ei, long long pos, int is64) {
    if (is64) return (int)((const long long*)ei)[pos];
    return ((const int*)ei)[pos];
}

// ---------------- vector global reductions (sm_90+) -------------------------
__device__ __forceinline__ void red_add_v4(float* p, float4 v) {
    asm volatile("red.global.add.v4.f32 [%0], {%1,%2,%3,%4};"
                 :: "l"(p), "f"(v.x), "f"(v.y), "f"(v.z), "f"(v.w) : "memory");
}
__device__ __forceinline__ void red_add_v2(float* p, float a, float b) {
    asm volatile("red.global.add.v2.f32 [%0], {%1,%2};"
                 :: "l"(p), "f"(a), "f"(b) : "memory");
}

// ---------------- init: zero accum, deg=1 (self loop), dtype detect ---------
__global__ void k_init(const int* __restrict__ ei32, int n) {
    long long i = (long long)blockIdx.x * blockDim.x + threadIdx.x;
    if (i == 0) {
        int all_zero = 1;
#pragma unroll 8
        for (int t = 0; t < 64; t++)
            if (ei32[2 * t + 1] != 0) { all_zero = 0; break; }
        g_is64 = all_zero;
    }
    long long tot = (long long)n * H1DIM;
    if (i < tot) g_h1[i] = 0.f;
    if (i < (long long)n * H2DIM) g_h2[i] = 0.f;
    if (i < n) g_deg[i] = 1.0f;   // self loop contributes 1 to dst degree
}

// ---------------- degree over edges -----------------------------------------
__global__ void k_degree(const void* __restrict__ ei, int E) {
    int e = blockIdx.x * blockDim.x + threadIdx.x;
    if (e >= E) return;
    int is64 = g_is64;
    int d = edge_at(ei, (long long)E + e, is64);
    atomicAdd(&g_deg[d], 1.0f);
}

__global__ void k_dinv(int n) {
    int i = blockIdx.x * blockDim.x + threadIdx.x;
    if (i < n) g_dinv[i] = rsqrtf(g_deg[i]);
}

// ---------------- GEMM: xw = dinv * (x @ W1)   [n,165]x[165,128] ------------
// 128x128 block tile, BK=16, 256 threads, 8x8 outputs/thread (scalar FFMA).
// Inner loop per kk: 2 broadcast LDS.128 (Xs) + 2 LDS.128 (Ws) + 64 FFMA.
#define GBM 128
#define GBK 16
__global__ void __launch_bounds__(256, 2)
k_gemm1(const float* __restrict__ x, const float* __restrict__ W1, int n) {
    __shared__ float Xs[GBK * GBM];     // [kk][row]  8 KB
    __shared__ float Ws[GBK * H1DIM];   // [kk][col]  8 KB

    const int tid = threadIdx.x;
    const int tx  = tid & 15;           // cols tx*8 .. tx*8+7
    const int ty  = tid >> 4;           // rows ty*8 .. ty*8+7
    const int m0  = blockIdx.x * GBM;

    float acc[8][8];
#pragma unroll
    for (int i = 0; i < 8; i++)
#pragma unroll
        for (int j = 0; j < 8; j++) acc[i][j] = 0.f;

    for (int kb = 0; kb < FDIM; kb += GBK) {
        // ---- W tile: thread loads row kk=tid>>4, cols (tid&15)*8 .. +7 ----
        {
            int kk   = tid >> 4;
            int col0 = (tid & 15) * 8;
            int kg   = kb + kk;
            float4 wa = make_float4(0.f, 0.f, 0.f, 0.f), wb = wa;
            if (kg < FDIM) {
                const float4* wr = (const float4*)(W1 + (long long)kg * H1DIM + col0);
                wa = wr[0]; wb = wr[1];
            }
            *(float4*)&Ws[kk * H1DIM + col0]     = wa;
            *(float4*)&Ws[kk * H1DIM + col0 + 4] = wb;
        }
        // ---- X tile transposed: row r=tid>>1, k strip (tid&1)*8 ----
        {
            int r   = tid >> 1;
            int kk0 = (tid & 1) * 8;
            int gm  = m0 + r;
            const float* xr = x + (long long)gm * FDIM + kb + kk0;
#pragma unroll
            for (int j = 0; j < 8; j++) {
                int kg = kb + kk0 + j;
                float v = (gm < n && kg < FDIM) ? xr[j] : 0.f;
                Xs[(kk0 + j) * GBM + r] = v;
            }
        }
        __syncthreads();

#pragma unroll
        for (int kk = 0; kk < GBK; kk++) {
            float4 xa = *(const float4*)&Xs[kk * GBM + ty * 8];
            float4 xb = *(const float4*)&Xs[kk * GBM + ty * 8 + 4];
            float4 wa = *(const float4*)&Ws[kk * H1DIM + tx * 8];
            float4 wb = *(const float4*)&Ws[kk * H1DIM + tx * 8 + 4];
            float xv[8] = {xa.x, xa.y, xa.z, xa.w, xb.x, xb.y, xb.z, xb.w};
            float wv[8] = {wa.x, wa.y, wa.z, wa.w, wb.x, wb.y, wb.z, wb.w};
#pragma unroll
            for (int i = 0; i < 8; i++)
#pragma unroll
                for (int j = 0; j < 8; j++)
                    acc[i][j] += xv[i] * wv[j];
        }
        __syncthreads();
    }

    // ---- epilogue: scale row by dinv[row], store ----
#pragma unroll
    for (int i = 0; i < 8; i++) {
        int gm = m0 + ty * 8 + i;
        if (gm >= n) break;
        float di = g_dinv[gm];
        float4* o = (float4*)&g_xw[(long long)gm * H1DIM + tx * 8];
        o[0] = make_float4(acc[i][0] * di, acc[i][1] * di,
                           acc[i][2] * di, acc[i][3] * di);
        o[1] = make_float4(acc[i][4] * di, acc[i][5] * di,
                           acc[i][6] * di, acc[i][7] * di);
    }
}

// ---------------- scatter1: raw1[dst] += xw[src]  (norm-free) ---------------
#define EPW 2
__global__ void __launch_bounds__(512) k_scatter1(const void* __restrict__ ei,
                                                  int E, int n) {
    long long w = ((long long)blockIdx.x * blockDim.x + threadIdx.x) >> 5;
    int lane = threadIdx.x & 31;
    long long tot  = (long long)E + n;
    long long base = w * EPW;
    if (base >= tot) return;
    int is64 = g_is64;

    int s[EPW], d[EPW];
#pragma unroll
    for (int j = 0; j < EPW; j++) {
        long long e = base + j;
        if (e >= tot) { s[j] = -1; continue; }
        if (e < E) {
            s[j] = edge_at(ei, e, is64);
            d[j] = edge_at(ei, (long long)E + e, is64);
        } else {
            s[j] = d[j] = (int)(e - E);   // self loop
        }
    }
    float4 v[EPW];
#pragma unroll
    for (int j = 0; j < EPW; j++)
        if (s[j] >= 0)
            v[j] = ((const float4*)&g_xw[(long long)s[j] * H1DIM])[lane];
#pragma unroll
    for (int j = 0; j < EPW; j++)
        if (s[j] >= 0)
            red_add_v4(&g_h1[(long long)d[j] * H1DIM + lane * 4], v[j]);
}

// ---------------- layer2: h2w = dinv * (relu(dinv*raw1 + b1) @ W2) ----------
__global__ void k_layer2(const float* __restrict__ b1,
                         const float* __restrict__ W2, int n) {
    int node = (int)(((long long)blockIdx.x * blockDim.x + threadIdx.x) >> 5);
    int lane = threadIdx.x & 31;
    if (node >= n) return;
    float di = g_dinv[node];
    float4 v = ((const float4*)&g_h1[(long long)node * H1DIM])[lane];
    float4 b = ((const float4*)b1)[lane];
    v.x = fmaxf(v.x * di + b.x, 0.f);
    v.y = fmaxf(v.y * di + b.y, 0.f);
    v.z = fmaxf(v.z * di + b.z, 0.f);
    v.w = fmaxf(v.w * di + b.w, 0.f);
    float4 wa = ((const float4*)W2)[lane * 2 + 0];   // rows l4+0, l4+1
    float4 wb = ((const float4*)W2)[lane * 2 + 1];   // rows l4+2, l4+3
    float a0 = v.x * wa.x + v.y * wa.z + v.z * wb.x + v.w * wb.z;
    float a1 = v.x * wa.y + v.y * wa.w + v.z * wb.y + v.w * wb.w;
#pragma unroll
    for (int off = 16; off > 0; off >>= 1) {
        a0 += __shfl_xor_sync(0xFFFFFFFFu, a0, off);
        a1 += __shfl_xor_sync(0xFFFFFFFFu, a1, off);
    }
    if (lane == 0) {
        g_h2w[(long long)node * 2 + 0] = a0 * di;
        g_h2w[(long long)node * 2 + 1] = a1 * di;
    }
}

// ---------------- scatter2: raw2[dst] += h2w[src]  (norm-free) --------------
__global__ void __launch_bounds__(512) k_scatter2(const void* __restrict__ ei,
                                                  int E, int n) {
    long long e = (long long)blockIdx.x * blockDim.x + threadIdx.x;
    long long tot = (long long)E + n;
    if (e >= tot) return;
    int is64 = g_is64;
    int s, d;
    if (e < E) {
        s = edge_at(ei, e, is64);
        d = edge_at(ei, (long long)E + e, is64);
    } else {
        s = d = (int)(e - E);
    }
    float2 v = *(const float2*)&g_h2w[(long long)s * 2];
    red_add_v2(&g_h2[(long long)d * 2], v.x, v.y);
}

// ---------------- head: out = sigmoid(relu(dinv*raw2+b2) @ Wc + bc) ---------
__global__ void k_head(const float* __restrict__ b2,
                       const float* __restrict__ Wc,
                       const float* __restrict__ bc,
                       float* __restrict__ out, int n) {
    int i = blockIdx.x * blockDim.x + threadIdx.x;
    if (i >= n) return;
    float di = g_dinv[i];
    float z0 = fmaxf(g_h2[(long long)i * 2 + 0] * di + b2[0], 0.f);
    float z1 = fmaxf(g_h2[(long long)i * 2 + 1] * di + b2[1], 0.f);
    float o = z0 * Wc[0] + z1 * Wc[1] + bc[0];
    out[i] = 1.0f / (1.0f + __expf(-o));
}

// ----------------------------------------------------------------------------
extern "C" void kernel_launch(void* const* d_in, const int* in_sizes, int n_in,
                              void* d_out, int out_size) {
    const float* x   = (const float*)d_in[0];
    const void*  ei  = d_in[1];
    const float* W1  = (const float*)d_in[2];
    const float* b1  = (const float*)d_in[3];
    const float* W2  = (const float*)d_in[4];
    const float* b2  = (const float*)d_in[5];
    const float* Wc  = (const float*)d_in[6];
    const float* bc  = (const float*)d_in[7];
    float*       out = (float*)d_out;

    const int n = in_sizes[0] / FDIM;       // 100000
    const int E = in_sizes[1] / 2;          // 1600000

    const int T = 256;
    long long initN = (long long)n * H1DIM;
    k_init<<<(unsigned)((initN + T - 1) / T), T>>>((const int*)ei, n);
    k_degree<<<(E + T - 1) / T, T>>>(ei, E);
    k_dinv<<<(n + T - 1) / T, T>>>(n);
    k_gemm1<<<(n + GBM - 1) / GBM, 256>>>(x, W1, n);

    long long tot   = (long long)E + n;
    long long warps = (tot + EPW - 1) / EPW;
    long long thr1  = warps * 32;
    k_scatter1<<<(unsigned)((thr1 + 511) / 512), 512>>>(ei, E, n);

    long long thr2 = (long long)n * 32;
    k_layer2<<<(unsigned)((thr2 + T - 1) / T), T>>>(b1, W2, n);

    k_scatter2<<<(unsigned)((tot + 511) / 512), 512>>>(ei, E, n);
    k_head<<<(n + T - 1) / T, T>>>(b2, Wc, bc, out, n);
}